// round 8
// baseline (speedup 1.0000x reference)
#include <cuda_runtime.h>

// SE_loss_w_threshold: h,v (8,16384,128) fp32, N scalar.
// out (10 fp32): [mean_Rp, R_per_user[0..7], sum(R_per_user)]
// R8: block-shared tile. 4 warps cooperate on ONE batch (t split 4-ways),
// tile 8.4KB/block double-buffered -> 8 blocks/SM (32 warps/SM), cp.async
// depth-2 pipeline per warp, cross-warp A-combine via smem scratch,
// rotating tail warp. GRID=1184.

#define NUSER 8
#define BATCH 16384
#define ROWF  132                      // padded row stride (floats), conflict-free
#define TILEF (NUSER * ROWF)           // 1056 floats per array
#define BUF   (2 * TILEF)              // h+v tile: 2112 floats (8448 B)
#define NBLK  1184                     // 148 SMs * 8 blocks/SM, single wave
#define THREADS 128

typedef unsigned long long u64;

__device__ double gAcc[9];
__device__ unsigned int gCount = 0;

__device__ __forceinline__ u64 ffma2(u64 a, u64 b, u64 c) {
    u64 d;
    asm("fma.rn.f32x2 %0, %1, %2, %3;" : "=l"(d) : "l"(a), "l"(b), "l"(c));
    return d;
}
__device__ __forceinline__ float hsum2(u64 a) {
    float2 f;
    asm("mov.b64 {%0, %1}, %2;" : "=f"(f.x), "=f"(f.y) : "l"(a));
    return f.x + f.y;
}

#define DOT(re, ip, in, hl, hh, vl, vh)            \
    re = ffma2((hl).x, (vl).x, re);                \
    re = ffma2((hl).y, (vl).y, re);                \
    re = ffma2((hh).x, (vh).x, re);                \
    re = ffma2((hh).y, (vh).y, re);                \
    ip = ffma2((hh).x, (vl).x, ip);                \
    ip = ffma2((hh).y, (vl).y, ip);                \
    in = ffma2((hl).x, (vh).x, in);                \
    in = ffma2((hl).y, (vh).y, in);

// warp wid stages h,v rows {2wid, 2wid+1} of batch b into the buffer (4 cp.async)
__device__ __forceinline__ void stage(const float* __restrict__ hg,
                                      const float* __restrict__ vg,
                                      int b, int wid, int lane, unsigned bufa)
{
    #pragma unroll
    for (int q = 0; q < 4; q++) {
        const int id  = wid * 4 + q;
        const int u   = id >> 1;
        const int arr = id & 1;
        const float* src = (arr ? vg : hg)
                         + (((size_t)(u * BATCH + b)) << 7) + (lane << 2);
        const unsigned dst = bufa
            + (unsigned)((arr * TILEF + u * ROWF + (lane << 2)) * 4);
        asm volatile("cp.async.cg.shared.global [%0], [%1], 16;"
                     :: "r"(dst), "l"(src));
    }
    asm volatile("cp.async.commit_group;");
}

__global__ __launch_bounds__(THREADS, 8)
void se_fused_kernel(const float* __restrict__ hg,
                     const float* __restrict__ vg,
                     const float* __restrict__ Np,
                     float* __restrict__ out, int out_size)
{
    __shared__ __align__(16) float sh[2 * BUF];     // two block-shared buffers
    __shared__ __align__(16) float red[4][16][12];  // per-warp A partials + nrm
    __shared__ double sAcc[9];
    __shared__ int sLast;

    const int tid  = threadIdx.x;
    const int lane = tid & 31;
    const int wid  = tid >> 5;

    if (tid < 9) sAcc[tid] = 0.0;   // first read is after later barriers

    const float Nval = __ldg(Np);

    // lane decomposition within each warp: c = col pair, a = row pair, k2 = t-split
    const int c  = lane & 3;
    const int a  = (lane >> 2) & 3;
    const int k2 = lane >> 4;

    const unsigned base0 = (unsigned)__cvta_generic_to_shared(sh);

    // pipeline fill: first two batches of this block
    stage(hg, vg, blockIdx.x, wid, lane, base0);
    stage(hg, vg, blockIdx.x + NBLK, wid, lane, base0 + BUF * 4);

    float accRp = 0.0f, accR0 = 0.0f, accR1 = 0.0f;

    int buf = 0, it = 0;
    for (int b = blockIdx.x; b < BATCH; b += NBLK, buf ^= 1, it++) {
        asm volatile("cp.async.wait_group 1;" ::: "memory");
        __syncthreads();                       // all warps' data for b visible

        float* wb = sh + buf * BUF;
        const float* hr0 = wb + (2 * a) * ROWF;
        const float* hr1 = hr0 + ROWF;
        const float* vc0 = wb + TILEF + (2 * c) * ROWF;
        const float* vc1 = vc0 + ROWF;

        // ---- ||v||^2 partial: this warp's own staged v rows (2wid, 2wid+1) ----
        u64 nrm2 = 0ULL;
        #pragma unroll
        for (int r = 0; r < 2; r++) {
            const ulonglong2 vv = *(const ulonglong2*)
                (wb + TILEF + (2 * wid + r) * ROWF + (lane << 2));
            nrm2 = ffma2(vv.x, vv.x, nrm2);
            nrm2 = ffma2(vv.y, vv.y, nrm2);
        }

        // ---- 2x2 complex-dot block over this warp's t-eighth (m-blocks 2wid,2wid+1) ----
        u64 re00 = 0, ip00 = 0, in00 = 0;
        u64 re01 = 0, ip01 = 0, in01 = 0;
        u64 re10 = 0, ip10 = 0, in10 = 0;
        u64 re11 = 0, ip11 = 0, in11 = 0;

        #pragma unroll
        for (int m = 0; m < 2; m++) {
            const int off = k2 * 4 + (wid * 2 + m) * 8;
            const ulonglong2 h0l = *(const ulonglong2*)(hr0 + off);
            const ulonglong2 h0h = *(const ulonglong2*)(hr0 + off + 64);
            const ulonglong2 h1l = *(const ulonglong2*)(hr1 + off);
            const ulonglong2 h1h = *(const ulonglong2*)(hr1 + off + 64);
            const ulonglong2 v0l = *(const ulonglong2*)(vc0 + off);
            const ulonglong2 v0h = *(const ulonglong2*)(vc0 + off + 64);
            const ulonglong2 v1l = *(const ulonglong2*)(vc1 + off);
            const ulonglong2 v1h = *(const ulonglong2*)(vc1 + off + 64);

            DOT(re00, ip00, in00, h0l, h0h, v0l, v0h)
            DOT(re01, ip01, in01, h0l, h0h, v1l, v1h)
            DOT(re10, ip10, in10, h1l, h1h, v0l, v0h)
            DOT(re11, ip11, in11, h1l, h1h, v1l, v1h)
        }

        // collapse f32x2 + k2 halves
        float Ar00 = hsum2(re00), Ai00 = hsum2(ip00) - hsum2(in00);
        float Ar01 = hsum2(re01), Ai01 = hsum2(ip01) - hsum2(in01);
        float Ar10 = hsum2(re10), Ai10 = hsum2(ip10) - hsum2(in10);
        float Ar11 = hsum2(re11), Ai11 = hsum2(ip11) - hsum2(in11);

        Ar00 += __shfl_xor_sync(0xffffffffu, Ar00, 16);
        Ai00 += __shfl_xor_sync(0xffffffffu, Ai00, 16);
        Ar01 += __shfl_xor_sync(0xffffffffu, Ar01, 16);
        Ai01 += __shfl_xor_sync(0xffffffffu, Ai01, 16);
        Ar10 += __shfl_xor_sync(0xffffffffu, Ar10, 16);
        Ai10 += __shfl_xor_sync(0xffffffffu, Ai10, 16);
        Ar11 += __shfl_xor_sync(0xffffffffu, Ar11, 16);
        Ai11 += __shfl_xor_sync(0xffffffffu, Ai11, 16);

        // warp-level nrm partial (rows 2wid..2wid+1, all t)
        float nrm = hsum2(nrm2);
        #pragma unroll
        for (int o = 16; o; o >>= 1)
            nrm += __shfl_xor_sync(0xffffffffu, nrm, o);

        // ---- publish warp partials (lanes k2==0; lane == pair == 4a+c) ----
        if (k2 == 0) {
            float* slot = &red[wid][lane][0];
            *(float4*)(slot)     = make_float4(Ar00, Ai00, Ar01, Ai01);
            *(float4*)(slot + 4) = make_float4(Ar10, Ai10, Ar11, Ai11);
            if (lane == 0) red[wid][0][8] = nrm;
        }
        __syncthreads();                       // partials visible; buf fully read

        // refill the just-consumed buffer with batch b + 2*NBLK
        const int bp = b + 2 * NBLK;
        if (bp < BATCH)
            stage(hg, vg, bp, wid, lane, base0 + (unsigned)buf * (BUF * 4));
        else
            asm volatile("cp.async.commit_group;");   // keep group count aligned

        // ---- tail on rotating warp (16 lanes = pair index) ----
        if (wid == (it & 3) && lane < 16) {
            const int p = lane;
            float4 x0 = *(const float4*)&red[0][p][0];
            float4 x1 = *(const float4*)&red[0][p][4];
            #pragma unroll
            for (int w = 1; w < 4; w++) {
                const float4 y0 = *(const float4*)&red[w][p][0];
                const float4 y1 = *(const float4*)&red[w][p][4];
                x0.x += y0.x; x0.y += y0.y; x0.z += y0.z; x0.w += y0.w;
                x1.x += y1.x; x1.y += y1.y; x1.z += y1.z; x1.w += y1.w;
            }
            const float nrmT = red[0][0][8] + red[1][0][8]
                             + red[2][0][8] + red[3][0][8];

            const float p00 = fmaf(x0.x, x0.x, x0.y * x0.y);
            const float p01 = fmaf(x0.z, x0.z, x0.w * x0.w);
            const float p10 = fmaf(x1.x, x1.x, x1.y * x1.y);
            const float p11 = fmaf(x1.z, x1.z, x1.w * x1.w);

            float s0 = p00 + p01;
            float s1 = p10 + p11;
            s0 += __shfl_xor_sync(0x0000ffffu, s0, 1);
            s1 += __shfl_xor_sync(0x0000ffffu, s1, 1);
            s0 += __shfl_xor_sync(0x0000ffffu, s0, 2);
            s1 += __shfl_xor_sync(0x0000ffffu, s1, 2);

            const int aa = p >> 2, cc = p & 3;
            if (aa == cc) {                    // diagonal pairs: users 2aa, 2aa+1
                const float scale2 = 8.0f / nrmT;
                const float sinr0 = __fdividef(p00 * scale2, s0 - p00 + Nval);
                const float sinr1 = __fdividef(p11 * scale2, s1 - p11 + Nval);
                const float R0 = __log2f(1.0f + sinr0);
                const float R1 = __log2f(1.0f + sinr1);
                accR0 += R0;
                accR1 += R1;
                accRp += __exp10f(0.3f - R0) - R0
                       + __exp10f(0.3f - R1) - R1;
            }
        }
    }

    // ---- flush per-thread accumulators (all 4 warps held tail turns) ----
    if (lane < 16) {
        const int aa = lane >> 2, cc = lane & 3;
        if (aa == cc) {
            atomicAdd(&sAcc[0],          (double)accRp);
            atomicAdd(&sAcc[1 + 2 * aa], (double)accR0);
            atomicAdd(&sAcc[2 + 2 * aa], (double)accR1);
        }
    }
    __syncthreads();

    if (tid < 9) atomicAdd(&gAcc[tid], sAcc[tid]);
    __threadfence();
    __syncthreads();

    if (tid == 0) {
        const unsigned old = atomicInc(&gCount, NBLK - 1);
        sLast = (old == NBLK - 1) ? 1 : 0;
    }
    __syncthreads();

    if (sLast && tid == 0) {
        __threadfence();
        const double inv = 1.0 / (double)BATCH;
        double r[9];
        #pragma unroll
        for (int i = 0; i < 9; i++) {
            r[i] = __ldcg(&gAcc[i]);
            __stcg(&gAcc[i], 0.0);
        }
        double s = 0.0;
        #pragma unroll
        for (int i = 1; i < 9; i++) s += r[i] * inv;
        if (out_size >= 1) out[0] = (float)(r[0] * inv);
        if (out_size >= 10) {
            #pragma unroll
            for (int i = 0; i < 8; i++) out[1 + i] = (float)(r[1 + i] * inv);
            out[9] = (float)s;
        }
    }
}

extern "C" void kernel_launch(void* const* d_in, const int* in_sizes, int n_in,
                              void* d_out, int out_size)
{
    const float* h = (const float*)d_in[0];
    const float* v = (const float*)d_in[1];
    const float* N = (const float*)d_in[2];
    float* out = (float*)d_out;

    se_fused_kernel<<<NBLK, THREADS>>>(h, v, N, out, out_size);
}

// round 9
// speedup vs baseline: 1.2705x; 1.2705x over previous
#include <cuda_runtime.h>

// SE_loss_w_threshold: h,v (8,16384,128) fp32, N scalar.
// out (10 fp32): [mean_Rp, R_per_user[0..7], sum(R_per_user)]
// R9 = R6 + register-level software pipelining: two accumulator sets so the
// shuffle/MUFU reduction of batch n overlaps (same basic block) with the
// LDS/FFMA dot loop of batch n+1. launch_bounds(128,3) frees regs to 170.

#define NUSER 8
#define BATCH 16384
#define ROWF  132
#define TILEF (NUSER * ROWF)
#define WARP_TILE (2 * TILEF)
#define WPB   4
#define THREADS (WPB * 32)
#define GRID  444                      // 148 SMs * 3 blocks/SM (smem-capped)
#define BUF_STRIDE_B (WPB * WARP_TILE * 4)
#define SMEM_BYTES   (2 * WPB * WARP_TILE * 4)

typedef unsigned long long u64;

__device__ double gAcc[9];
__device__ unsigned int gCount = 0;

__device__ __forceinline__ u64 ffma2(u64 a, u64 b, u64 c) {
    u64 d;
    asm("fma.rn.f32x2 %0, %1, %2, %3;" : "=l"(d) : "l"(a), "l"(b), "l"(c));
    return d;
}
__device__ __forceinline__ float hsum2(u64 a) {
    float2 f;
    asm("mov.b64 {%0, %1}, %2;" : "=f"(f.x), "=f"(f.y) : "l"(a));
    return f.x + f.y;
}

#define DOT(re, ip, in, hl, hh, vl, vh)            \
    re = ffma2((hl).x, (vl).x, re);                \
    re = ffma2((hl).y, (vl).y, re);                \
    re = ffma2((hh).x, (vh).x, re);                \
    re = ffma2((hh).y, (vh).y, re);                \
    ip = ffma2((hh).x, (vl).x, ip);                \
    ip = ffma2((hh).y, (vl).y, ip);                \
    in = ffma2((hl).x, (vh).x, in);                \
    in = ffma2((hl).y, (vh).y, in);

struct Acc {
    u64 nrm2;
    u64 re00, ip00, in00;
    u64 re01, ip01, in01;
    u64 re10, ip10, in10;
    u64 re11, ip11, in11;
};

// stage one batch's tiles into the given smem buffer + commit
__device__ __forceinline__ void stage(const float* __restrict__ hg,
                                      const float* __restrict__ vg,
                                      int b, int lane, unsigned bufa)
{
    const int lo = lane << 2;
    const unsigned sHa = bufa + (unsigned)(lo * 4);
    const unsigned sVa = sHa + (unsigned)(TILEF * 4);
    #pragma unroll
    for (int u = 0; u < NUSER; u++) {
        const int base = ((u * BATCH + b) << 7) + lo;
        asm volatile("cp.async.cg.shared.global [%0], [%1], 16;"
                     :: "r"(sHa + (unsigned)(u * ROWF * 4)), "l"(hg + base));
        asm volatile("cp.async.cg.shared.global [%0], [%1], 16;"
                     :: "r"(sVa + (unsigned)(u * ROWF * 4)), "l"(vg + base));
    }
    asm volatile("cp.async.commit_group;");
}

// LDS + FFMA phase: accumulate one batch's dot partials into A
__device__ __forceinline__ void dots(Acc& A, const float* __restrict__ wb,
                                     int a, int c, int t0, int lane)
{
    const float* hr0 = wb + (2 * a) * ROWF;
    const float* hr1 = hr0 + ROWF;
    const float* vc0 = wb + TILEF + (2 * c) * ROWF;
    const float* vc1 = vc0 + ROWF;

    A.nrm2 = 0ULL;
    A.re00 = A.ip00 = A.in00 = 0ULL;
    A.re01 = A.ip01 = A.in01 = 0ULL;
    A.re10 = A.ip10 = A.in10 = 0ULL;
    A.re11 = A.ip11 = A.in11 = 0ULL;

    #pragma unroll
    for (int u = 0; u < NUSER; u++) {
        const ulonglong2 vv = *(const ulonglong2*)(wb + TILEF + u * ROWF + (lane << 2));
        A.nrm2 = ffma2(vv.x, vv.x, A.nrm2);
        A.nrm2 = ffma2(vv.y, vv.y, A.nrm2);
    }
    #pragma unroll
    for (int m = 0; m < 8; m++) {
        const int off = t0 + m * 8;
        const ulonglong2 h0l = *(const ulonglong2*)(hr0 + off);
        const ulonglong2 h0h = *(const ulonglong2*)(hr0 + off + 64);
        const ulonglong2 h1l = *(const ulonglong2*)(hr1 + off);
        const ulonglong2 h1h = *(const ulonglong2*)(hr1 + off + 64);
        const ulonglong2 v0l = *(const ulonglong2*)(vc0 + off);
        const ulonglong2 v0h = *(const ulonglong2*)(vc0 + off + 64);
        const ulonglong2 v1l = *(const ulonglong2*)(vc1 + off);
        const ulonglong2 v1h = *(const ulonglong2*)(vc1 + off + 64);

        DOT(A.re00, A.ip00, A.in00, h0l, h0h, v0l, v0h)
        DOT(A.re01, A.ip01, A.in01, h0l, h0h, v1l, v1h)
        DOT(A.re10, A.ip10, A.in10, h1l, h1h, v0l, v0h)
        DOT(A.re11, A.ip11, A.in11, h1l, h1h, v1l, v1h)
    }
}

// shuffle + scalar-tail phase (register-only, independent of smem)
__device__ __forceinline__ void reduceTail(const Acc& A, float Nval,
                                           int a, int c, int k2,
                                           float& accRp, float& accR0, float& accR1)
{
    float nrm = hsum2(A.nrm2);
    #pragma unroll
    for (int o = 16; o; o >>= 1)
        nrm += __shfl_xor_sync(0xffffffffu, nrm, o);

    float Ar00 = hsum2(A.re00), Ai00 = hsum2(A.ip00) - hsum2(A.in00);
    float Ar01 = hsum2(A.re01), Ai01 = hsum2(A.ip01) - hsum2(A.in01);
    float Ar10 = hsum2(A.re10), Ai10 = hsum2(A.ip10) - hsum2(A.in10);
    float Ar11 = hsum2(A.re11), Ai11 = hsum2(A.ip11) - hsum2(A.in11);

    Ar00 += __shfl_xor_sync(0xffffffffu, Ar00, 16);
    Ai00 += __shfl_xor_sync(0xffffffffu, Ai00, 16);
    Ar01 += __shfl_xor_sync(0xffffffffu, Ar01, 16);
    Ai01 += __shfl_xor_sync(0xffffffffu, Ai01, 16);
    Ar10 += __shfl_xor_sync(0xffffffffu, Ar10, 16);
    Ai10 += __shfl_xor_sync(0xffffffffu, Ai10, 16);
    Ar11 += __shfl_xor_sync(0xffffffffu, Ar11, 16);
    Ai11 += __shfl_xor_sync(0xffffffffu, Ai11, 16);

    const float p00 = fmaf(Ar00, Ar00, Ai00 * Ai00);
    const float p01 = fmaf(Ar01, Ar01, Ai01 * Ai01);
    const float p10 = fmaf(Ar10, Ar10, Ai10 * Ai10);
    const float p11 = fmaf(Ar11, Ar11, Ai11 * Ai11);

    const float d0 = p00, d1 = p11;     // valid on lanes c==a

    float s0 = p00 + p01;
    float s1 = p10 + p11;
    s0 += __shfl_xor_sync(0xffffffffu, s0, 1);
    s1 += __shfl_xor_sync(0xffffffffu, s1, 1);
    s0 += __shfl_xor_sync(0xffffffffu, s0, 2);
    s1 += __shfl_xor_sync(0xffffffffu, s1, 2);

    if (c == a && k2 == 0) {
        const float scale2 = 8.0f / nrm;
        const float sinr0 = __fdividef(d0 * scale2, s0 - d0 + Nval);
        const float sinr1 = __fdividef(d1 * scale2, s1 - d1 + Nval);
        const float R0 = __log2f(1.0f + sinr0);
        const float R1 = __log2f(1.0f + sinr1);
        accR0 += R0;
        accR1 += R1;
        accRp += __exp10f(0.3f - R0) - R0
               + __exp10f(0.3f - R1) - R1;
    }
}

__global__ __launch_bounds__(THREADS, 3)
void se_fused_kernel(const float* __restrict__ hg,
                     const float* __restrict__ vg,
                     const float* __restrict__ Np,
                     float* __restrict__ out, int out_size)
{
    extern __shared__ __align__(16) float sh[];
    __shared__ double sAcc[9];
    __shared__ int sLast;

    const int tid  = threadIdx.x;
    const int lane = tid & 31;
    const int wid  = tid >> 5;

    if (tid < 9) sAcc[tid] = 0.0;
    __syncthreads();

    const int gw = blockIdx.x * WPB + wid;
    const int nw = GRID * WPB;

    float* buf0f = sh + wid * WARP_TILE;
    float* buf1f = sh + (WPB + wid) * WARP_TILE;
    const unsigned buf0a = (unsigned)__cvta_generic_to_shared(buf0f);
    const unsigned buf1a = (unsigned)__cvta_generic_to_shared(buf1f);

    const float Nval = __ldg(Np);

    const int c  = lane & 3;
    const int a  = (lane >> 2) & 3;
    const int k2 = lane >> 4;
    const int t0 = k2 * 4;

    float accRp = 0.0f, accR0 = 0.0f, accR1 = 0.0f;
    Acc A, B;

    // ---- prologue: fill pipe, compute dots for first batch ----
    stage(hg, vg, gw, lane, buf0a);            // G0
    stage(hg, vg, gw + nw, lane, buf1a);       // G1 (gw+nw < BATCH always)
    asm volatile("cp.async.wait_group 1;" ::: "memory");
    __syncwarp();
    dots(A, buf0f, a, c, t0, lane);
    __syncwarp();
    stage(hg, vg, gw + 2 * nw, lane, buf0a);   // G2 (gw+2nw < BATCH always)

    int b = gw;
    int curbuf = 1;                            // buffer holding b+nw

    for (;;) {
        // -------- half 1: dots->B overlapped with reduce(A) --------
        int bn = b + nw;
        if (bn >= BATCH) { reduceTail(A, Nval, a, c, k2, accRp, accR0, accR1); break; }
        asm volatile("cp.async.wait_group 1;" ::: "memory");
        __syncwarp();
        dots(B, curbuf ? buf1f : buf0f, a, c, t0, lane);
        reduceTail(A, Nval, a, c, k2, accRp, accR0, accR1);   // independent: interleaved
        __syncwarp();
        {
            const int bp = bn + 2 * nw;
            if (bp < BATCH) {
                stage(hg, vg, bp, lane, curbuf ? buf1a : buf0a);
            } else {
                asm volatile("cp.async.commit_group;");
            }
        }
        b = bn; curbuf ^= 1;

        // -------- half 2: dots->A overlapped with reduce(B) --------
        bn = b + nw;
        if (bn >= BATCH) { reduceTail(B, Nval, a, c, k2, accRp, accR0, accR1); break; }
        asm volatile("cp.async.wait_group 1;" ::: "memory");
        __syncwarp();
        dots(A, curbuf ? buf1f : buf0f, a, c, t0, lane);
        reduceTail(B, Nval, a, c, k2, accRp, accR0, accR1);
        __syncwarp();
        {
            const int bp = bn + 2 * nw;
            if (bp < BATCH) {
                stage(hg, vg, bp, lane, curbuf ? buf1a : buf0a);
            } else {
                asm volatile("cp.async.commit_group;");
            }
        }
        b = bn; curbuf ^= 1;
    }

    // ---- block-level reduction ----
    if (c == a && k2 == 0) {
        atomicAdd(&sAcc[0],         (double)accRp);
        atomicAdd(&sAcc[1 + 2 * a], (double)accR0);
        atomicAdd(&sAcc[2 + 2 * a], (double)accR1);
    }
    __syncthreads();

    if (tid < 9) atomicAdd(&gAcc[tid], sAcc[tid]);
    __threadfence();
    __syncthreads();

    if (tid == 0) {
        const unsigned old = atomicInc(&gCount, GRID - 1);
        sLast = (old == GRID - 1) ? 1 : 0;
    }
    __syncthreads();

    if (sLast && tid == 0) {
        __threadfence();
        const double inv = 1.0 / (double)BATCH;
        double r[9];
        #pragma unroll
        for (int i = 0; i < 9; i++) {
            r[i] = __ldcg(&gAcc[i]);
            __stcg(&gAcc[i], 0.0);
        }
        double s = 0.0;
        #pragma unroll
        for (int i = 1; i < 9; i++) s += r[i] * inv;
        if (out_size >= 1) out[0] = (float)(r[0] * inv);
        if (out_size >= 10) {
            #pragma unroll
            for (int i = 0; i < 8; i++) out[1 + i] = (float)(r[1 + i] * inv);
            out[9] = (float)s;
        }
    }
}

extern "C" void kernel_launch(void* const* d_in, const int* in_sizes, int n_in,
                              void* d_out, int out_size)
{
    const float* h = (const float*)d_in[0];
    const float* v = (const float*)d_in[1];
    const float* N = (const float*)d_in[2];
    float* out = (float*)d_out;

    cudaFuncSetAttribute(se_fused_kernel,
                         cudaFuncAttributeMaxDynamicSharedMemorySize, SMEM_BYTES);
    se_fused_kernel<<<GRID, THREADS, SMEM_BYTES>>>(h, v, N, out, out_size);
}